// round 16
// baseline (speedup 1.0000x reference)
#include <cuda_runtime.h>
#include <cuda_bf16.h>
#include <stdint.h>
#include <stddef.h>

namespace {
constexpr int kC       = 64;
constexpr int kN       = 512 * 512;     // 262144
constexpr int kChunk   = 128;
constexpr int kNChunks = kN / kChunk;   // 2048
constexpr int kGrid1   = 880;           // 440 blocks per batch
constexpr int kBPB     = kGrid1 / 2;    // 440
constexpr int kQ5      = 2048 - 4 * kBPB;   // 288 blocks get 5 chunks, rest 4
constexpr int kP1      = 136;           // syrk bf16 smem pitch (LDSM-aligned)
constexpr int kPM      = 72;            // bf16 M pitch (LDSM-aligned: 144B = 9*16)
constexpr int kPA      = 65;            // attn f32 pitch
constexpr int kPS      = 128;           // apply fp32 stage pitch
constexpr int kPB      = 136;           // apply bf16 tile pitch (272B = 17*16, LDSM ok)
constexpr int kAttnSmem  = 4 * kC * kPA * 4;   // Xc, W0, W1, T
constexpr int kApplyDyn  = kC * kPS * 4;       // single fp32 stage (32.8KB)
}

__device__ float g_part[kGrid1][kC][kC];     // per-block U = 0.5*HH^T
__device__ float g_xcov[2][kC][kC];          // summed U (Xc = U + U^T at use)
__device__ __nv_bfloat16 g_M[2][kC][kC];

__device__ __forceinline__ void mma_bf16(float c[4], const uint32_t a[4],
                                         const uint32_t b[2]) {
    asm volatile(
        "mma.sync.aligned.m16n8k16.row.col.f32.bf16.bf16.f32 "
        "{%0,%1,%2,%3}, {%4,%5,%6,%7}, {%8,%9}, {%0,%1,%2,%3};\n"
        : "+f"(c[0]), "+f"(c[1]), "+f"(c[2]), "+f"(c[3])
        : "r"(a[0]), "r"(a[1]), "r"(a[2]), "r"(a[3]), "r"(b[0]), "r"(b[1]));
}

__device__ __forceinline__ uint32_t smem_u32(const void* p) {
    return (uint32_t)__cvta_generic_to_shared(p);
}

__device__ __forceinline__ void ldsm_x4(uint32_t& r0, uint32_t& r1,
                                        uint32_t& r2, uint32_t& r3,
                                        uint32_t addr) {
    asm volatile("ldmatrix.sync.aligned.m8n8.x4.shared.b16 {%0,%1,%2,%3}, [%4];"
                 : "=r"(r0), "=r"(r1), "=r"(r2), "=r"(r3) : "r"(addr));
}

__device__ __forceinline__ void ldsm_x4_trans(uint32_t& r0, uint32_t& r1,
                                              uint32_t& r2, uint32_t& r3,
                                              uint32_t addr) {
    asm volatile("ldmatrix.sync.aligned.m8n8.x4.trans.shared.b16 {%0,%1,%2,%3}, [%4];"
                 : "=r"(r0), "=r"(r1), "=r"(r2), "=r"(r3) : "r"(addr));
}

__device__ __forceinline__ uint32_t pack_bf16x2(float lo, float hi) {
    __nv_bfloat162 h = __floats2bfloat162_rn(lo, hi);
    return *reinterpret_cast<uint32_t*>(&h);
}

__device__ __forceinline__ void cp_async16(float* smem_dst, const float* gmem_src) {
    uint32_t s = (uint32_t)__cvta_generic_to_shared(smem_dst);
    asm volatile("cp.async.cg.shared.global [%0], [%1], 16;\n"
                 :: "r"(s), "l"(gmem_src));
}
__device__ __forceinline__ void cp_async_commit() {
    asm volatile("cp.async.commit_group;\n");
}
template <int N>
__device__ __forceinline__ void cp_async_wait() {
    asm volatile("cp.async.wait_group %0;\n" :: "n"(N));
}

// balanced contiguous partition of 2048 chunks over 440 block-slots
__device__ __forceinline__ void chunk_range(int cb, int& c0, int& q) {
    if (cb < kQ5) { q = 5; c0 = cb * 5; }
    else          { q = 4; c0 = kQ5 * 5 + (cb - kQ5) * 4; }
}

// ------------------------------------------------------------------ pass 1
// U partials: U = 0.5*H H^T, H = bf16(x). Fragments via ldmatrix. (frozen)
__global__ __launch_bounds__(256, 3) void syrk_kernel(const float* __restrict__ x) {
    __shared__ __nv_bfloat16 sH[kC][kP1];

    const int tid = threadIdx.x;
    const int warp = tid >> 5, lane = tid & 31;
    const int b = blockIdx.x & 1;
    const float* xb = x + (size_t)b * kC * kN;
    const int i0 = warp >> 2, j0 = warp & 3;   // C tile coords
    const int rsel = lane & 15;
    const int csel = (lane >> 4) << 3;

    int c0, q;
    chunk_range(blockIdx.x >> 1, c0, q);

    float accS[2][2][4];
#pragma unroll
    for (int s = 0; s < 2; s++)
#pragma unroll
        for (int n = 0; n < 2; n++)
#pragma unroll
            for (int r = 0; r < 4; r++) accS[s][n][r] = 0.f;

    float4 buf[8];
    {
        const int col0 = c0 * kChunk;
#pragma unroll
        for (int i = 0; i < 8; i++) {
            const int idx4 = tid + (i << 8);
            buf[i] = *reinterpret_cast<const float4*>(
                xb + (size_t)(idx4 >> 5) * kN + col0 + ((idx4 & 31) << 2));
        }
    }

    for (int k = 0; k < q; k++) {
#pragma unroll
        for (int i = 0; i < 8; i++) {
            const int idx4 = tid + (i << 8);
            const int ch = idx4 >> 5, cc = (idx4 & 31) << 2;
            *reinterpret_cast<__nv_bfloat162*>(&sH[ch][cc]) =
                __floats2bfloat162_rn(buf[i].x, buf[i].y);
            *reinterpret_cast<__nv_bfloat162*>(&sH[ch][cc + 2]) =
                __floats2bfloat162_rn(buf[i].z, buf[i].w);
        }
        __syncthreads();

        if (k + 1 < q) {
            const int col0 = (c0 + k + 1) * kChunk;
#pragma unroll
            for (int i = 0; i < 8; i++) {
                const int idx4 = tid + (i << 8);
                buf[i] = *reinterpret_cast<const float4*>(
                    xb + (size_t)(idx4 >> 5) * kN + col0 + ((idx4 & 31) << 2));
            }
        }

#pragma unroll
        for (int ks = 0; ks < 8; ks++) {
            const int coff = (ks << 4) + csel;
            uint32_t m0, m1, m2, m3;
            ldsm_x4(m0, m1, m2, m3, smem_u32(&sH[(j0 << 4) + rsel][coff]));
            uint32_t bA[2] = {m0, m2};
            uint32_t bB[2] = {m1, m3};
#pragma unroll
            for (int s = 0; s < 2; s++) {
                uint32_t aH[4];
                ldsm_x4(aH[0], aH[1], aH[2], aH[3],
                        smem_u32(&sH[((i0 + (s << 1)) << 4) + rsel][coff]));
                mma_bf16(accS[s][0], aH, bA);
                mma_bf16(accS[s][1], aH, bB);
            }
        }
        __syncthreads();
    }

    const int g = lane >> 2, t2 = (lane & 3) << 1;
#pragma unroll
    for (int s = 0; s < 2; s++) {
        const int r0 = ((i0 + (s << 1)) << 4) + g;
#pragma unroll
        for (int nh = 0; nh < 2; nh++) {
            const int cb2 = (j0 << 4) + (nh << 3) + t2;
            g_part[blockIdx.x][r0][cb2]         = 0.5f * accS[s][nh][0];
            g_part[blockIdx.x][r0][cb2 + 1]     = 0.5f * accS[s][nh][1];
            g_part[blockIdx.x][r0 + 8][cb2]     = 0.5f * accS[s][nh][2];
            g_part[blockIdx.x][r0 + 8][cb2 + 1] = 0.5f * accS[s][nh][3];
        }
    }
}

// ------------------------------------------------------------------ pass 1b (frozen)
__global__ __launch_bounds__(256) void reduce_kernel() {
    const int b   = blockIdx.x >> 6;
    const int r   = blockIdx.x & 63;
    const int col = threadIdx.x & 63;
    const int sub = threadIdx.x >> 6;
    __shared__ float sAcc[4][kC];

    constexpr int kPer = kBPB / 4;             // 110
    const int j0 = sub * kPer;
    float s0 = 0.f, s1 = 0.f;
#pragma unroll 2
    for (int i = 0; i < kPer; i += 2) {
        s0 += g_part[b + 2 * (j0 + i)][r][col];
        s1 += g_part[b + 2 * (j0 + i + 1)][r][col];
    }
    sAcc[sub][col] = s0 + s1;
    __syncthreads();
    if (sub == 0)
        g_xcov[b][r][col] = (sAcc[0][col] + sAcc[1][col]) +
                            (sAcc[2][col] + sAcc[3][col]);
}

// ------------------------------------------------------------------ pass 2 (frozen)
__global__ __launch_bounds__(512) void attn_kernel(
    const float* __restrict__ Wq, const float* __restrict__ Wk,
    const float* __restrict__ Wv, const float* __restrict__ Wp,
    const float* __restrict__ rescale)
{
    extern __shared__ float dsm[];
    float* sXc = dsm;
    float* sW0 = dsm + kC * kPA;
    float* sW1 = dsm + 2 * kC * kPA;
    float* sT  = dsm + 3 * kC * kPA;
    __shared__ float sAttn[kC][16];
    __shared__ float sPart[8][kC];
    __shared__ float sSq[kC];

    const int b = blockIdx.x, tid = threadIdx.x;
    const int m = tid & 63, oct = tid >> 6;

    for (int idx = tid; idx < kC * kC; idx += 512) {
        const int r = idx >> 6, c = idx & 63;
        sXc[r * kPA + c] = g_xcov[b][r][c] + g_xcov[b][c][r];
        sW0[r * kPA + c] = Wq[idx];
    }
    __syncthreads();

    {
        float wreg[8];
#pragma unroll
        for (int t = 0; t < 8; t++) wreg[t] = __ldg(&Wk[((oct + 8 * t) << 6) + m]);
        float acc[8];
#pragma unroll
        for (int t = 0; t < 8; t++) acc[t] = 0.f;
#pragma unroll 8
        for (int j = 0; j < 64; j++) {
            const float xv = sXc[j * kPA + m];
#pragma unroll
            for (int t = 0; t < 8; t++) acc[t] += sW0[(oct + 8 * t) * kPA + j] * xv;
        }
#pragma unroll
        for (int t = 0; t < 8; t++) {
            sT[(oct + 8 * t) * kPA + m] = acc[t];
            sW1[(oct + 8 * t) * kPA + m] = wreg[t];
        }
    }
    __syncthreads();

    float wvreg[8];
#pragma unroll
    for (int t = 0; t < 8; t++) wvreg[t] = __ldg(&Wv[((oct + 8 * t) << 6) + m]);
    {
        float s = 0.f;
#pragma unroll
        for (int jj = 0; jj < 8; jj++) {
            const int j = oct * 8 + jj;
            s += sT[m * kPA + j] * sW0[m * kPA + j];
        }
        sPart[oct][m] = s;
    }
    for (int idx = tid; idx < 1024; idx += 512) {
        const int h = idx >> 8, d = (idx >> 4) & 15, e = idx & 15;
        const int kc = (h << 4) + d, qc = (h << 4) + e;
        float s = 0.f;
#pragma unroll 8
        for (int mm = 0; mm < 64; mm++)
            s += sW1[kc * kPA + mm] * sT[qc * kPA + mm];
        sAttn[kc][e] = s;
    }
    __syncthreads();
    if (tid < 64) {
        float s = 0.f;
#pragma unroll
        for (int qd = 0; qd < 8; qd++) s += sPart[qd][tid];
        sSq[tid] = fmaxf(sqrtf(fmaxf(s, 0.f)), 1e-12f);
    }

    {
        float acc[8];
#pragma unroll
        for (int t = 0; t < 8; t++) acc[t] = 0.f;
#pragma unroll 8
        for (int j = 0; j < 64; j++) {
            const float xv = sXc[j * kPA + m];
#pragma unroll
            for (int t = 0; t < 8; t++) acc[t] += sW1[(oct + 8 * t) * kPA + j] * xv;
        }
#pragma unroll
        for (int t = 0; t < 8; t++) {
            sT[(oct + 8 * t) * kPA + m] = acc[t];
            sW0[(oct + 8 * t) * kPA + m] = wvreg[t];
        }
    }
    __syncthreads();

    float wpreg[8];
#pragma unroll
    for (int t = 0; t < 8; t++) wpreg[t] = __ldg(&Wp[((oct + 8 * t) << 6) + m]);
    {
        float s = 0.f;
#pragma unroll
        for (int jj = 0; jj < 8; jj++) {
            const int j = oct * 8 + jj;
            s += sT[m * kPA + j] * sW1[m * kPA + j];
        }
        sPart[oct][m] = s;
    }
    __syncthreads();

    if (tid < 64) {
        float s = 0.f;
#pragma unroll
        for (int qd = 0; qd < 8; qd++) s += sPart[qd][tid];
        const float nk = fmaxf(sqrtf(fmaxf(s, 0.f)), 1e-12f);
        const int kc = tid, h = kc >> 4;
        const float rs = __ldg(&rescale[h]);
        const float invk = 1.f / nk;
        float logit[16], mx = -1e30f;
#pragma unroll
        for (int e = 0; e < 16; e++) {
            logit[e] = sAttn[kc][e] * invk / sSq[(kc & 48) + e] * rs;
            mx = fmaxf(mx, logit[e]);
        }
        float sum = 0.f;
#pragma unroll
        for (int e = 0; e < 16; e++) { logit[e] = expf(logit[e] - mx); sum += logit[e]; }
        const float inv = 1.f / sum;
#pragma unroll
        for (int e = 0; e < 16; e++) sAttn[kc][e] = logit[e] * inv;
    }
#pragma unroll
    for (int t = 0; t < 8; t++)
        sW1[(oct + 8 * t) * kPA + m] = wpreg[t];
    __syncthreads();

    for (int idx = tid; idx < kC * kC; idx += 512) {
        const int r = idx >> 6, cc = idx & 63, h = r >> 4;
        float s = 0.f;
#pragma unroll
        for (int e = 0; e < 16; e++)
            s += sAttn[r][e] * sW0[((h << 4) + e) * kPA + cc];
        sT[r * kPA + cc] = s;
    }
    __syncthreads();

    {
        float acc[8];
#pragma unroll
        for (int t = 0; t < 8; t++) acc[t] = 0.f;
#pragma unroll 8
        for (int j = 0; j < 64; j++) {
            const float xv = sT[j * kPA + m];
#pragma unroll
            for (int t = 0; t < 8; t++) acc[t] += sW1[(oct + 8 * t) * kPA + j] * xv;
        }
#pragma unroll
        for (int t = 0; t < 8; t++)
            g_M[b][oct + 8 * t][m] = __float2bfloat16(acc[t]);
    }
}

// ------------------------------------------------------------------ pass 3
// apply v7b: single fp32 stage (cp.async landing) -> bf16 tile (convert once,
// pitch 136 = 16B-aligned rows for LDSM) -> B via ldmatrix.trans;
// residual re-read from global (L2-hot).
__global__ __launch_bounds__(256, 3) void apply_kernel(
    const float* __restrict__ x, const float* __restrict__ bp,
    float* __restrict__ out)
{
    __shared__ __nv_bfloat16 sM[kC][kPM];
    __shared__ __nv_bfloat16 sXb[kC][kPB];
    extern __shared__ float stage[];           // [64][128]

    const int tid = threadIdx.x;
    const int warp = tid >> 5, lane = tid & 31;
    const int g = lane >> 2, t2 = (lane & 3) << 1;
    const int rsel = lane & 15, csel = (lane >> 4) << 3;
    const int gid = blockIdx.x;
    const int b = gid >> 9;                  // 512 block-slots per batch
    const int c0idx = gid & 511;             // chunks c0idx + k*512, k=0..3
    const float* xb = x + (size_t)b * kC * kN;
    float* ob = out + (size_t)b * kC * kN;

    for (int idx = tid; idx < kC * kC; idx += 256)
        sM[idx >> 6][idx & 63] = g_M[b][idx >> 6][idx & 63];

    float bpv[4][2];
#pragma unroll
    for (int ot = 0; ot < 4; ot++) {
        bpv[ot][0] = __ldg(&bp[(ot << 4) + g]);
        bpv[ot][1] = __ldg(&bp[(ot << 4) + g + 8]);
    }

    const int ch8 = tid >> 5, c48 = (lane << 2);

    // ldmatrix.trans address for this lane: covers (k 0-15) x (two 8-pos groups)
    const int tr_ch  = ((lane >> 3) & 1) << 3 | (lane & 7);   // 0..15
    const int tr_pos = ((lane >> 4) << 6) + (warp << 3);      // wcol or wcol+64

    // issue chunk 0
    {
        const int col0 = c0idx * kChunk;
#pragma unroll
        for (int i = 0; i < 8; i++) {
            const int ch = ch8 + (i << 3);
            cp_async16(stage + ch * kPS + c48,
                       xb + (size_t)ch * kN + col0 + c48);
        }
        cp_async_commit();
    }

#pragma unroll
    for (int k = 0; k < 4; k++) {
        const int col0 = (c0idx + (k << 9)) * kChunk;

        cp_async_wait<0>();
        __syncthreads();        // stage k ready; prev chunk's sXb reads done

        // convert fp32 stage -> bf16 tile
#pragma unroll
        for (int i = 0; i < 8; i++) {
            const int idx4 = tid + (i << 8);
            const int ch = idx4 >> 5, c4 = (idx4 & 31) << 2;
            const float4 v = *reinterpret_cast<const float4*>(&stage[ch * kPS + c4]);
            uint2 p;
            p.x = pack_bf16x2(v.x, v.y);
            p.y = pack_bf16x2(v.z, v.w);
            *reinterpret_cast<uint2*>(&sXb[ch][c4]) = p;
        }
        __syncthreads();        // bf16 tile complete; stage free

        if (k + 1 < 4) {        // overlap next chunk's loads with mma
            const int ncol0 = (c0idx + ((k + 1) << 9)) * kChunk;
#pragma unroll
            for (int i = 0; i < 8; i++) {
                const int ch = ch8 + (i << 3);
                cp_async16(stage + ch * kPS + c48,
                           xb + (size_t)ch * kN + ncol0 + c48);
            }
            cp_async_commit();
        }

        float acc[2][4][4];
#pragma unroll
        for (int s = 0; s < 2; s++)
#pragma unroll
            for (int ot = 0; ot < 4; ot++)
#pragma unroll
                for (int r = 0; r < 4; r++) acc[s][ot][r] = 0.f;

#pragma unroll
        for (int ks = 0; ks < 4; ks++) {
            uint32_t b0, b1, b2, b3;
            ldsm_x4_trans(b0, b1, b2, b3,
                          smem_u32(&sXb[(ks << 4) + tr_ch][tr_pos]));
            uint32_t bA[2] = {b0, b1};   // s = 0 (cols wcol..wcol+7)
            uint32_t bB[2] = {b2, b3};   // s = 1 (cols wcol+64..)
#pragma unroll
            for (int ot = 0; ot < 4; ot++) {
                uint32_t a[4];
                ldsm_x4(a[0], a[1], a[2], a[3],
                        smem_u32(&sM[(ot << 4) + rsel][(ks << 4) + csel]));
                mma_bf16(acc[0][ot], a, bA);
                mma_bf16(acc[1][ot], a, bB);
            }
        }

        // epilogue: residual from global (L2-hot), bias, store
#pragma unroll
        for (int s = 0; s < 2; s++) {
            const int c0 = ((warp + (s << 3)) << 3) + t2;
#pragma unroll
            for (int ot = 0; ot < 4; ot++) {
                const int r0 = (ot << 4) + g;
                const float2 x0 = *reinterpret_cast<const float2*>(
                    &xb[(size_t)r0 * kN + col0 + c0]);
                const float2 x1 = *reinterpret_cast<const float2*>(
                    &xb[(size_t)(r0 + 8) * kN + col0 + c0]);
                float2 v0, v1;
                v0.x = acc[s][ot][0] + x0.x + bpv[ot][0];
                v0.y = acc[s][ot][1] + x0.y + bpv[ot][0];
                v1.x = acc[s][ot][2] + x1.x + bpv[ot][1];
                v1.y = acc[s][ot][3] + x1.y + bpv[ot][1];
                *reinterpret_cast<float2*>(&ob[(size_t)r0 * kN + col0 + c0]) = v0;
                *reinterpret_cast<float2*>(&ob[(size_t)(r0 + 8) * kN + col0 + c0]) = v1;
            }
        }
    }
}

// ------------------------------------------------------------------ launch
extern "C" void kernel_launch(void* const* d_in, const int* in_sizes, int n_in,
                              void* d_out, int out_size) {
    const float* x       = (const float*)d_in[0];
    const float* Wq      = (const float*)d_in[1];
    const float* Wk      = (const float*)d_in[2];
    const float* Wv      = (const float*)d_in[3];
    const float* Wp      = (const float*)d_in[4];
    const float* bp      = (const float*)d_in[5];
    const float* rescale = (const float*)d_in[6];
    float* out           = (float*)d_out;

    cudaFuncSetAttribute(attn_kernel,
                         cudaFuncAttributeMaxDynamicSharedMemorySize, kAttnSmem);
    cudaFuncSetAttribute(apply_kernel,
                         cudaFuncAttributeMaxDynamicSharedMemorySize, kApplyDyn);

    syrk_kernel<<<kGrid1, 256>>>(x);
    reduce_kernel<<<2 * kC, 256>>>();
    attn_kernel<<<2, 512, kAttnSmem>>>(Wq, Wk, Wv, Wp, rescale);
    apply_kernel<<<1024, 256, kApplyDyn>>>(x, bp, out);
}

// round 17
// speedup vs baseline: 1.3845x; 1.3845x over previous
#include <cuda_runtime.h>
#include <cuda_bf16.h>
#include <stdint.h>
#include <stddef.h>

namespace {
constexpr int kC       = 64;
constexpr int kN       = 512 * 512;     // 262144
constexpr int kChunk   = 128;
constexpr int kNChunks = kN / kChunk;   // 2048
constexpr int kGrid1   = 880;           // 440 blocks per batch
constexpr int kBPB     = kGrid1 / 2;    // 440
constexpr int kQ5      = 2048 - 4 * kBPB;   // 288 blocks get 5 chunks, rest 4
constexpr int kP1      = 136;           // syrk bf16 smem pitch (LDSM-aligned)
constexpr int kPF      = 132;           // apply f32 smem pitch
constexpr int kPM      = 72;            // bf16 M pitch (LDSM-aligned)
constexpr int kPA      = 65;            // attn f32 pitch
constexpr int kAttnSmem  = 4 * kC * kPA * 4;        // Xc, W0, W1, T
constexpr int kApplyDyn  = 2 * kC * kPF * 4;        // 2 fp32 pipeline stages
}

__device__ float g_part[kGrid1][kC][kC];     // per-block U = 0.5*HH^T
__device__ float g_xcov[2][kC][kC];          // summed U (Xc = U + U^T at use)
__device__ __nv_bfloat16 g_M[2][kC][kC];

__device__ __forceinline__ void mma_bf16(float c[4], const uint32_t a[4],
                                         const uint32_t b[2]) {
    asm volatile(
        "mma.sync.aligned.m16n8k16.row.col.f32.bf16.bf16.f32 "
        "{%0,%1,%2,%3}, {%4,%5,%6,%7}, {%8,%9}, {%0,%1,%2,%3};\n"
        : "+f"(c[0]), "+f"(c[1]), "+f"(c[2]), "+f"(c[3])
        : "r"(a[0]), "r"(a[1]), "r"(a[2]), "r"(a[3]), "r"(b[0]), "r"(b[1]));
}

__device__ __forceinline__ uint32_t smem_u32(const void* p) {
    return (uint32_t)__cvta_generic_to_shared(p);
}

__device__ __forceinline__ void ldsm_x4(uint32_t& r0, uint32_t& r1,
                                        uint32_t& r2, uint32_t& r3,
                                        uint32_t addr) {
    asm volatile("ldmatrix.sync.aligned.m8n8.x4.shared.b16 {%0,%1,%2,%3}, [%4];"
                 : "=r"(r0), "=r"(r1), "=r"(r2), "=r"(r3) : "r"(addr));
}

__device__ __forceinline__ uint32_t pack_bf16x2(float lo, float hi) {
    __nv_bfloat162 h = __floats2bfloat162_rn(lo, hi);
    return *reinterpret_cast<uint32_t*>(&h);
}

__device__ __forceinline__ void cp_async16(float* smem_dst, const float* gmem_src) {
    uint32_t s = (uint32_t)__cvta_generic_to_shared(smem_dst);
    asm volatile("cp.async.cg.shared.global [%0], [%1], 16;\n"
                 :: "r"(s), "l"(gmem_src));
}
__device__ __forceinline__ void cp_async_commit() {
    asm volatile("cp.async.commit_group;\n");
}
template <int N>
__device__ __forceinline__ void cp_async_wait() {
    asm volatile("cp.async.wait_group %0;\n" :: "n"(N));
}

// balanced contiguous partition of 2048 chunks over 440 block-slots
__device__ __forceinline__ void chunk_range(int cb, int& c0, int& q) {
    if (cb < kQ5) { q = 5; c0 = cb * 5; }
    else          { q = 4; c0 = kQ5 * 5 + (cb - kQ5) * 4; }
}

// ------------------------------------------------------------------ pass 1
// U partials: U = 0.5*H H^T, H = bf16(x). Double-buffered sH: one barrier
// per chunk; convert(k) overlaps other warps' mma(k-1).
__global__ __launch_bounds__(256, 3) void syrk_kernel(const float* __restrict__ x) {
    __shared__ __nv_bfloat16 sH[2][kC][kP1];

    const int tid = threadIdx.x;
    const int warp = tid >> 5, lane = tid & 31;
    const int b = blockIdx.x & 1;
    const float* xb = x + (size_t)b * kC * kN;
    const int i0 = warp >> 2, j0 = warp & 3;   // C tile coords
    const int rsel = lane & 15;
    const int csel = (lane >> 4) << 3;

    int c0, q;
    chunk_range(blockIdx.x >> 1, c0, q);

    float accS[2][2][4];
#pragma unroll
    for (int s = 0; s < 2; s++)
#pragma unroll
        for (int n = 0; n < 2; n++)
#pragma unroll
            for (int r = 0; r < 4; r++) accS[s][n][r] = 0.f;

    float4 buf[8];
    {
        const int col0 = c0 * kChunk;
#pragma unroll
        for (int i = 0; i < 8; i++) {
            const int idx4 = tid + (i << 8);
            buf[i] = *reinterpret_cast<const float4*>(
                xb + (size_t)(idx4 >> 5) * kN + col0 + ((idx4 & 31) << 2));
        }
    }

    for (int k = 0; k < q; k++) {
        const int p = k & 1;
#pragma unroll
        for (int i = 0; i < 8; i++) {
            const int idx4 = tid + (i << 8);
            const int ch = idx4 >> 5, cc = (idx4 & 31) << 2;
            *reinterpret_cast<__nv_bfloat162*>(&sH[p][ch][cc]) =
                __floats2bfloat162_rn(buf[i].x, buf[i].y);
            *reinterpret_cast<__nv_bfloat162*>(&sH[p][ch][cc + 2]) =
                __floats2bfloat162_rn(buf[i].z, buf[i].w);
        }
        __syncthreads();

        if (k + 1 < q) {                        // prefetch next chunk
            const int col0 = (c0 + k + 1) * kChunk;
#pragma unroll
            for (int i = 0; i < 8; i++) {
                const int idx4 = tid + (i << 8);
                buf[i] = *reinterpret_cast<const float4*>(
                    xb + (size_t)(idx4 >> 5) * kN + col0 + ((idx4 & 31) << 2));
            }
        }

#pragma unroll
        for (int ks = 0; ks < 8; ks++) {
            const int coff = (ks << 4) + csel;
            uint32_t m0, m1, m2, m3;
            ldsm_x4(m0, m1, m2, m3, smem_u32(&sH[p][(j0 << 4) + rsel][coff]));
            uint32_t bA[2] = {m0, m2};
            uint32_t bB[2] = {m1, m3};
#pragma unroll
            for (int s = 0; s < 2; s++) {
                uint32_t aH[4];
                ldsm_x4(aH[0], aH[1], aH[2], aH[3],
                        smem_u32(&sH[p][((i0 + (s << 1)) << 4) + rsel][coff]));
                mma_bf16(accS[s][0], aH, bA);
                mma_bf16(accS[s][1], aH, bB);
            }
        }
        // no trailing barrier: next convert writes the other buffer
    }

    const int g = lane >> 2, t2 = (lane & 3) << 1;
#pragma unroll
    for (int s = 0; s < 2; s++) {
        const int r0 = ((i0 + (s << 1)) << 4) + g;
#pragma unroll
        for (int nh = 0; nh < 2; nh++) {
            const int cb2 = (j0 << 4) + (nh << 3) + t2;
            g_part[blockIdx.x][r0][cb2]         = 0.5f * accS[s][nh][0];
            g_part[blockIdx.x][r0][cb2 + 1]     = 0.5f * accS[s][nh][1];
            g_part[blockIdx.x][r0 + 8][cb2]     = 0.5f * accS[s][nh][2];
            g_part[blockIdx.x][r0 + 8][cb2 + 1] = 0.5f * accS[s][nh][3];
        }
    }
}

// ------------------------------------------------------------------ pass 1b (frozen)
__global__ __launch_bounds__(256) void reduce_kernel() {
    const int b   = blockIdx.x >> 6;
    const int r   = blockIdx.x & 63;
    const int col = threadIdx.x & 63;
    const int sub = threadIdx.x >> 6;
    __shared__ float sAcc[4][kC];

    constexpr int kPer = kBPB / 4;             // 110
    const int j0 = sub * kPer;
    float s0 = 0.f, s1 = 0.f;
#pragma unroll 2
    for (int i = 0; i < kPer; i += 2) {
        s0 += g_part[b + 2 * (j0 + i)][r][col];
        s1 += g_part[b + 2 * (j0 + i + 1)][r][col];
    }
    sAcc[sub][col] = s0 + s1;
    __syncthreads();
    if (sub == 0)
        g_xcov[b][r][col] = (sAcc[0][col] + sAcc[1][col]) +
                            (sAcc[2][col] + sAcc[3][col]);
}

// ------------------------------------------------------------------ pass 2 (frozen)
__global__ __launch_bounds__(512) void attn_kernel(
    const float* __restrict__ Wq, const float* __restrict__ Wk,
    const float* __restrict__ Wv, const float* __restrict__ Wp,
    const float* __restrict__ rescale)
{
    extern __shared__ float dsm[];
    float* sXc = dsm;
    float* sW0 = dsm + kC * kPA;
    float* sW1 = dsm + 2 * kC * kPA;
    float* sT  = dsm + 3 * kC * kPA;
    __shared__ float sAttn[kC][16];
    __shared__ float sPart[8][kC];
    __shared__ float sSq[kC];

    const int b = blockIdx.x, tid = threadIdx.x;
    const int m = tid & 63, oct = tid >> 6;

    for (int idx = tid; idx < kC * kC; idx += 512) {
        const int r = idx >> 6, c = idx & 63;
        sXc[r * kPA + c] = g_xcov[b][r][c] + g_xcov[b][c][r];
        sW0[r * kPA + c] = Wq[idx];
    }
    __syncthreads();

    {
        float wreg[8];
#pragma unroll
        for (int t = 0; t < 8; t++) wreg[t] = __ldg(&Wk[((oct + 8 * t) << 6) + m]);
        float acc[8];
#pragma unroll
        for (int t = 0; t < 8; t++) acc[t] = 0.f;
#pragma unroll 8
        for (int j = 0; j < 64; j++) {
            const float xv = sXc[j * kPA + m];
#pragma unroll
            for (int t = 0; t < 8; t++) acc[t] += sW0[(oct + 8 * t) * kPA + j] * xv;
        }
#pragma unroll
        for (int t = 0; t < 8; t++) {
            sT[(oct + 8 * t) * kPA + m] = acc[t];
            sW1[(oct + 8 * t) * kPA + m] = wreg[t];
        }
    }
    __syncthreads();

    float wvreg[8];
#pragma unroll
    for (int t = 0; t < 8; t++) wvreg[t] = __ldg(&Wv[((oct + 8 * t) << 6) + m]);
    {
        float s = 0.f;
#pragma unroll
        for (int jj = 0; jj < 8; jj++) {
            const int j = oct * 8 + jj;
            s += sT[m * kPA + j] * sW0[m * kPA + j];
        }
        sPart[oct][m] = s;
    }
    for (int idx = tid; idx < 1024; idx += 512) {
        const int h = idx >> 8, d = (idx >> 4) & 15, e = idx & 15;
        const int kc = (h << 4) + d, qc = (h << 4) + e;
        float s = 0.f;
#pragma unroll 8
        for (int mm = 0; mm < 64; mm++)
            s += sW1[kc * kPA + mm] * sT[qc * kPA + mm];
        sAttn[kc][e] = s;
    }
    __syncthreads();
    if (tid < 64) {
        float s = 0.f;
#pragma unroll
        for (int qd = 0; qd < 8; qd++) s += sPart[qd][tid];
        sSq[tid] = fmaxf(sqrtf(fmaxf(s, 0.f)), 1e-12f);
    }

    {
        float acc[8];
#pragma unroll
        for (int t = 0; t < 8; t++) acc[t] = 0.f;
#pragma unroll 8
        for (int j = 0; j < 64; j++) {
            const float xv = sXc[j * kPA + m];
#pragma unroll
            for (int t = 0; t < 8; t++) acc[t] += sW1[(oct + 8 * t) * kPA + j] * xv;
        }
#pragma unroll
        for (int t = 0; t < 8; t++) {
            sT[(oct + 8 * t) * kPA + m] = acc[t];
            sW0[(oct + 8 * t) * kPA + m] = wvreg[t];
        }
    }
    __syncthreads();

    float wpreg[8];
#pragma unroll
    for (int t = 0; t < 8; t++) wpreg[t] = __ldg(&Wp[((oct + 8 * t) << 6) + m]);
    {
        float s = 0.f;
#pragma unroll
        for (int jj = 0; jj < 8; jj++) {
            const int j = oct * 8 + jj;
            s += sT[m * kPA + j] * sW1[m * kPA + j];
        }
        sPart[oct][m] = s;
    }
    __syncthreads();

    if (tid < 64) {
        float s = 0.f;
#pragma unroll
        for (int qd = 0; qd < 8; qd++) s += sPart[qd][tid];
        const float nk = fmaxf(sqrtf(fmaxf(s, 0.f)), 1e-12f);
        const int kc = tid, h = kc >> 4;
        const float rs = __ldg(&rescale[h]);
        const float invk = 1.f / nk;
        float logit[16], mx = -1e30f;
#pragma unroll
        for (int e = 0; e < 16; e++) {
            logit[e] = sAttn[kc][e] * invk / sSq[(kc & 48) + e] * rs;
            mx = fmaxf(mx, logit[e]);
        }
        float sum = 0.f;
#pragma unroll
        for (int e = 0; e < 16; e++) { logit[e] = expf(logit[e] - mx); sum += logit[e]; }
        const float inv = 1.f / sum;
#pragma unroll
        for (int e = 0; e < 16; e++) sAttn[kc][e] = logit[e] * inv;
    }
#pragma unroll
    for (int t = 0; t < 8; t++)
        sW1[(oct + 8 * t) * kPA + m] = wpreg[t];
    __syncthreads();

    for (int idx = tid; idx < kC * kC; idx += 512) {
        const int r = idx >> 6, cc = idx & 63, h = r >> 4;
        float s = 0.f;
#pragma unroll
        for (int e = 0; e < 16; e++)
            s += sAttn[r][e] * sW0[((h << 4) + e) * kPA + cc];
        sT[r * kPA + cc] = s;
    }
    __syncthreads();

    {
        float acc[8];
#pragma unroll
        for (int t = 0; t < 8; t++) acc[t] = 0.f;
#pragma unroll 8
        for (int j = 0; j < 64; j++) {
            const float xv = sT[j * kPA + m];
#pragma unroll
            for (int t = 0; t < 8; t++) acc[t] += sW1[(oct + 8 * t) * kPA + j] * xv;
        }
#pragma unroll
        for (int t = 0; t < 8; t++)
            g_M[b][oct + 8 * t][m] = __float2bfloat16(acc[t]);
    }
}

// ------------------------------------------------------------------ pass 3
// out = x + M x + bp. R14 version (best measured: 65.8us): 2-stage fp32
// cp.async double buffer, bfrag scalar-pack, sM via LDSM.
__global__ __launch_bounds__(256, 3) void apply_kernel(
    const float* __restrict__ x, const float* __restrict__ bp,
    float* __restrict__ out)
{
    __shared__ __nv_bfloat16 sM[kC][kPM];
    extern __shared__ float dsmA[];
    float* sX0 = dsmA;                 // [64][132]
    float* sX1 = dsmA + kC * kPF;

    const int tid = threadIdx.x;
    const int warp = tid >> 5, lane = tid & 31;
    const int g = lane >> 2, t2 = (lane & 3) << 1;
    const int rsel = lane & 15, csel = (lane >> 4) << 3;
    const int gid = blockIdx.x;
    const int b = gid >> 9;                  // 512 block-slots per batch
    const int c0idx = gid & 511;             // chunks c0idx + k*512, k=0..3
    const float* xb = x + (size_t)b * kC * kN;
    float* ob = out + (size_t)b * kC * kN;

    for (int idx = tid; idx < kC * kC; idx += 256)
        sM[idx >> 6][idx & 63] = g_M[b][idx >> 6][idx & 63];

    float bpv[4][2];
#pragma unroll
    for (int ot = 0; ot < 4; ot++) {
        bpv[ot][0] = __ldg(&bp[(ot << 4) + g]);
        bpv[ot][1] = __ldg(&bp[(ot << 4) + g + 8]);
    }

    const int ch8 = tid >> 5, c48 = (lane << 2);

    {
        const int col0 = c0idx * kChunk;
#pragma unroll
        for (int i = 0; i < 8; i++) {
            const int ch = ch8 + (i << 3);
            cp_async16(sX0 + ch * kPF + c48,
                       xb + (size_t)ch * kN + col0 + c48);
        }
        cp_async_commit();
    }

#pragma unroll
    for (int k = 0; k < 4; k++) {
        const int col0 = (c0idx + (k << 9)) * kChunk;
        float* sXp = (k & 1) ? sX1 : sX0;

        if (k + 1 < 4) {
            const int ncol0 = (c0idx + ((k + 1) << 9)) * kChunk;
            float* sXn = ((k + 1) & 1) ? sX1 : sX0;
#pragma unroll
            for (int i = 0; i < 8; i++) {
                const int ch = ch8 + (i << 3);
                cp_async16(sXn + ch * kPF + c48,
                           xb + (size_t)ch * kN + ncol0 + c48);
            }
            cp_async_commit();
            cp_async_wait<1>();
        } else {
            cp_async_wait<0>();
        }
        __syncthreads();

        float acc[2][4][4];
#pragma unroll
        for (int s = 0; s < 2; s++)
#pragma unroll
            for (int ot = 0; ot < 4; ot++)
#pragma unroll
                for (int r = 0; r < 4; r++) acc[s][ot][r] = 0.f;

        uint32_t bfrag[2][4][2];
#pragma unroll
        for (int s = 0; s < 2; s++) {
            const int colb = ((warp + (s << 3)) << 3) + g;
#pragma unroll
            for (int ks = 0; ks < 4; ks++) {
                const int kc = (ks << 4) + t2;
                bfrag[s][ks][0] = pack_bf16x2(sXp[kc * kPF + colb],
                                              sXp[(kc + 1) * kPF + colb]);
                bfrag[s][ks][1] = pack_bf16x2(sXp[(kc + 8) * kPF + colb],
                                              sXp[(kc + 9) * kPF + colb]);
            }
        }

#pragma unroll
        for (int ot = 0; ot < 4; ot++) {
#pragma unroll
            for (int ks = 0; ks < 4; ks++) {
                uint32_t a[4];
                ldsm_x4(a[0], a[1], a[2], a[3],
                        smem_u32(&sM[(ot << 4) + rsel][(ks << 4) + csel]));
                mma_bf16(acc[0][ot], a, bfrag[0][ks]);
                mma_bf16(acc[1][ot], a, bfrag[1][ks]);
            }
        }

#pragma unroll
        for (int s = 0; s < 2; s++) {
            const int c0 = ((warp + (s << 3)) << 3) + t2;
#pragma unroll
            for (int ot = 0; ot < 4; ot++) {
                const int r0 = (ot << 4) + g;
                float2 v0, v1;
                v0.x = acc[s][ot][0] + sXp[r0 * kPF + c0]           + bpv[ot][0];
                v0.y = acc[s][ot][1] + sXp[r0 * kPF + c0 + 1]       + bpv[ot][0];
                v1.x = acc[s][ot][2] + sXp[(r0 + 8) * kPF + c0]     + bpv[ot][1];
                v1.y = acc[s][ot][3] + sXp[(r0 + 8) * kPF + c0 + 1] + bpv[ot][1];
                *reinterpret_cast<float2*>(&ob[(size_t)r0 * kN + col0 + c0]) = v0;
                *reinterpret_cast<float2*>(&ob[(size_t)(r0 + 8) * kN + col0 + c0]) = v1;
            }
        }
        __syncthreads();
    }
}

// ------------------------------------------------------------------ launch
extern "C" void kernel_launch(void* const* d_in, const int* in_sizes, int n_in,
                              void* d_out, int out_size) {
    const float* x       = (const float*)d_in[0];
    const float* Wq      = (const float*)d_in[1];
    const float* Wk      = (const float*)d_in[2];
    const float* Wv      = (const float*)d_in[3];
    const float* Wp      = (const float*)d_in[4];
    const float* bp      = (const float*)d_in[5];
    const float* rescale = (const float*)d_in[6];
    float* out           = (float*)d_out;

    cudaFuncSetAttribute(attn_kernel,
                         cudaFuncAttributeMaxDynamicSharedMemorySize, kAttnSmem);
    cudaFuncSetAttribute(apply_kernel,
                         cudaFuncAttributeMaxDynamicSharedMemorySize, kApplyDyn);

    syrk_kernel<<<kGrid1, 256>>>(x);
    reduce_kernel<<<2 * kC, 256>>>();
    attn_kernel<<<2, 512, kAttnSmem>>>(Wq, Wk, Wv, Wp, rescale);
    apply_kernel<<<1024, 256, kApplyDyn>>>(x, bp, out);
}